// round 7
// baseline (speedup 1.0000x reference)
#include <cuda_runtime.h>
#include <cuda_fp16.h>

#define NUM_PL 50000
#define NUM_TR 100000
#define NUM_AR 10000
#define OFF_TR NUM_PL
#define OFF_AR (NUM_PL + NUM_TR)
#define NTOT   (NUM_PL + NUM_TR + NUM_AR)
#define HID    64
#define NADJ   4200000
#define SCAN_B 1024
#define NB     ((NTOT + SCAN_B - 1) / SCAN_B)   // 157

typedef unsigned long long ull;

// GEMM dynamic smem: Wd dup [64][66] ull + rows [128][36] float
#define WD_LD   66
#define ROWS_LD 36
#define GEMM_SMEM (64 * WD_LD * 8 + 128 * ROWS_LD * 4)   // 52224 B

// -------- scratch (device globals; no runtime allocation) --------
__device__ __align__(16) float  g_x  [(size_t)NTOT * HID];
__device__ __align__(16) float  g_y  [(size_t)NTOT * HID];
__device__ __align__(16) float  g_agg[(size_t)NTOT * HID];
__device__ __align__(16) __half g_h0 [(size_t)NTOT * HID];
__device__ __align__(16) __half g_h1 [(size_t)NTOT * HID];
__device__ int   g_deg [NTOT];
__device__ float g_rdeg[NTOT];
__device__ int   g_ptr [NTOT];
__device__ int   g_cur [NTOT];
__device__ __align__(16) int g_adj [NADJ];
__device__ int   g_bsum[NB];
__device__ int   g_boff[NB];

// -------- helpers --------
__device__ __forceinline__ ull dup_f32(float x) {
    ull r; asm("mov.b64 %0, {%1,%1};" : "=l"(r) : "f"(x)); return r;
}
__device__ __forceinline__ void ffma2(ull& d, ull a, ull b) {
    asm("fma.rn.f32x2 %0, %1, %2, %3;" : "=l"(d) : "l"(a), "l"(b), "l"(d));
}
__device__ __forceinline__ float2 unpack2(ull v) {
    float2 f; asm("mov.b64 {%0,%1}, %2;" : "=f"(f.x), "=f"(f.y) : "l"(v)); return f;
}
__device__ __forceinline__ float2 h2f(unsigned u) {
    return __half22float2(*(const __half2*)&u);
}
__device__ __forceinline__ __half2 u2h(unsigned u) {
    return *(const __half2*)&u;
}
__device__ __forceinline__ unsigned f2h2(float a, float b) {
    __half2 h = __floats2half2_rn(a, b);
    return *(const unsigned*)&h;
}

// -------- init playlist & artist rows --------
__global__ void init_emb_kernel(const float* __restrict__ pl_emb,
                                const float* __restrict__ ar_emb,
                                const float* __restrict__ type_emb) {
    int t = blockIdx.x * blockDim.x + threadIdx.x;
    int total = (NUM_PL + NUM_AR) * (HID / 4);
    if (t >= total) return;
    int node = t >> 4;
    int c    = (t & 15) * 4;
    const float* src; const float* ty; size_t row;
    if (node < NUM_PL) {
        src = pl_emb + (size_t)node * HID;
        row = (size_t)node * HID;
        ty  = type_emb;
    } else {
        int a = node - NUM_PL;
        src = ar_emb + (size_t)a * HID;
        row = (size_t)(OFF_AR + a) * HID;
        ty  = type_emb + 2 * HID;
    }
    float4 v  = *(const float4*)(src + c);
    float4 tv = *(const float4*)(ty  + c);
    v.x += tv.x; v.y += tv.y; v.z += tv.z; v.w += tv.w;
    *(float4*)(g_x + row + c) = v;
    uint2 h; h.x = f2h2(v.x, v.y); h.y = f2h2(v.z, v.w);
    *(uint2*)(g_h0 + row + c) = h;
}

__global__ void zero_deg_kernel() {
    int i = blockIdx.x * blockDim.x + threadIdx.x;
    if (i < NTOT) g_deg[i] = 0;
}

__global__ void deg_kernel(const int* __restrict__ s1, const int* __restrict__ d1, int n1,
                           const int* __restrict__ s2, const int* __restrict__ d2, int n2) {
    int e = blockIdx.x * blockDim.x + threadIdx.x;
    int a, b;
    if (e < n1)           { a = __ldg(s1 + e);               b = __ldg(d1 + e) + OFF_TR; }
    else if (e < n1 + n2) { a = __ldg(s2 + e - n1) + OFF_TR; b = __ldg(d2 + e - n1) + OFF_AR; }
    else return;
    atomicAdd(&g_deg[a], 1);
    atomicAdd(&g_deg[b], 1);
}

// -------- 3-pass scan --------
__device__ __forceinline__ int block_incl_scan(int v, int* warpsums) {
    int lane = threadIdx.x & 31, wid = threadIdx.x >> 5;
    int x = v;
#pragma unroll
    for (int o = 1; o < 32; o <<= 1) {
        int y = __shfl_up_sync(0xffffffffu, x, o);
        if (lane >= o) x += y;
    }
    if (lane == 31) warpsums[wid] = x;
    __syncthreads();
    if (threadIdx.x < 32) {
        int w = warpsums[threadIdx.x];
#pragma unroll
        for (int o = 1; o < 32; o <<= 1) {
            int y = __shfl_up_sync(0xffffffffu, w, o);
            if (threadIdx.x >= o) w += y;
        }
        warpsums[threadIdx.x] = w;
    }
    __syncthreads();
    if (wid > 0) x += warpsums[wid - 1];
    return x;
}

__global__ void scan_pass1() {
    __shared__ int warpsums[32];
    int i = blockIdx.x * SCAN_B + threadIdx.x;
    int v = (i < NTOT) ? g_deg[i] : 0;
    int x = block_incl_scan(v, warpsums);
    if (threadIdx.x == SCAN_B - 1) g_bsum[blockIdx.x] = x;
}

__global__ void scan_pass2() {
    __shared__ int warpsums[32];
    int i = threadIdx.x;
    int v = (i < NB) ? g_bsum[i] : 0;
    int x = block_incl_scan(v, warpsums);
    if (i < NB) g_boff[i] = x - v;
}

__global__ void scan_pass3() {
    __shared__ int warpsums[32];
    int i = blockIdx.x * SCAN_B + threadIdx.x;
    int v = (i < NTOT) ? g_deg[i] : 0;
    int x = block_incl_scan(v, warpsums);
    if (i < NTOT) {
        int excl = x - v + g_boff[blockIdx.x];
        g_ptr[i] = excl;
        g_cur[i] = excl;
        g_rdeg[i] = 1.0f / (float)(v > 0 ? v : 1);
    }
}

__global__ void fill_kernel(const int* __restrict__ s1, const int* __restrict__ d1, int n1,
                            const int* __restrict__ s2, const int* __restrict__ d2, int n2) {
    int e = blockIdx.x * blockDim.x + threadIdx.x;
    int a, b;
    if (e < n1)           { a = __ldg(s1 + e);               b = __ldg(d1 + e) + OFF_TR; }
    else if (e < n1 + n2) { a = __ldg(s2 + e - n1) + OFF_TR; b = __ldg(d2 + e - n1) + OFF_AR; }
    else return;
    int pa = atomicAdd(&g_cur[a], 1);
    g_adj[pa] = b;
    int pb = atomicAdd(&g_cur[b], 1);
    g_adj[pb] = a;
}

// -------- gather aggregation: 8 lanes/node, 8-neighbor unroll (MLP=8) --------
__global__ void gather_kernel(int layer) {
    const __half* __restrict__ H = layer ? g_h1 : g_h0;
    int t = blockIdx.x * blockDim.x + threadIdx.x;
    int node = t >> 3;
    if (node >= NTOT) return;
    int c = (t & 7) * 8;
    int beg = g_ptr[node];
    int d   = g_deg[node];
    float acc[8];
#pragma unroll
    for (int j = 0; j < 8; j++) acc[j] = 0.f;

    int i = 0;
    int mis = beg & 3;
    int peel = mis ? (4 - mis) : 0;
    if (peel > d) peel = d;
    for (; i < peel; i++) {
        int s = __ldg(g_adj + beg + i);
        uint4 v = *(const uint4*)(H + (size_t)s * HID + c);
#pragma unroll
        for (int q = 0; q < 4; q++) {
            float2 f = h2f((&v.x)[q]);
            acc[q * 2 + 0] += f.x; acc[q * 2 + 1] += f.y;
        }
    }
    for (; i + 8 <= d; i += 8) {
        int4 sA = *(const int4*)(g_adj + beg + i);
        int4 sB = *(const int4*)(g_adj + beg + i + 4);
        uint4 v0 = *(const uint4*)(H + (size_t)sA.x * HID + c);
        uint4 v1 = *(const uint4*)(H + (size_t)sA.y * HID + c);
        uint4 v2 = *(const uint4*)(H + (size_t)sA.z * HID + c);
        uint4 v3 = *(const uint4*)(H + (size_t)sA.w * HID + c);
        uint4 v4 = *(const uint4*)(H + (size_t)sB.x * HID + c);
        uint4 v5 = *(const uint4*)(H + (size_t)sB.y * HID + c);
        uint4 v6 = *(const uint4*)(H + (size_t)sB.z * HID + c);
        uint4 v7 = *(const uint4*)(H + (size_t)sB.w * HID + c);
#pragma unroll
        for (int q = 0; q < 4; q++) {
            __half2 sh0 = __hadd2(__hadd2(u2h((&v0.x)[q]), u2h((&v1.x)[q])),
                                  __hadd2(u2h((&v2.x)[q]), u2h((&v3.x)[q])));
            float2 f0 = __half22float2(sh0);
            acc[q * 2 + 0] += f0.x; acc[q * 2 + 1] += f0.y;
            __half2 sh1 = __hadd2(__hadd2(u2h((&v4.x)[q]), u2h((&v5.x)[q])),
                                  __hadd2(u2h((&v6.x)[q]), u2h((&v7.x)[q])));
            float2 f1 = __half22float2(sh1);
            acc[q * 2 + 0] += f1.x; acc[q * 2 + 1] += f1.y;
        }
    }
    for (; i + 4 <= d; i += 4) {
        int4 s = *(const int4*)(g_adj + beg + i);
        uint4 v0 = *(const uint4*)(H + (size_t)s.x * HID + c);
        uint4 v1 = *(const uint4*)(H + (size_t)s.y * HID + c);
        uint4 v2 = *(const uint4*)(H + (size_t)s.z * HID + c);
        uint4 v3 = *(const uint4*)(H + (size_t)s.w * HID + c);
#pragma unroll
        for (int q = 0; q < 4; q++) {
            __half2 sh = __hadd2(__hadd2(u2h((&v0.x)[q]), u2h((&v1.x)[q])),
                                 __hadd2(u2h((&v2.x)[q]), u2h((&v3.x)[q])));
            float2 f = __half22float2(sh);
            acc[q * 2 + 0] += f.x; acc[q * 2 + 1] += f.y;
        }
    }
    for (; i < d; i++) {
        int s = __ldg(g_adj + beg + i);
        uint4 v = *(const uint4*)(H + (size_t)s * HID + c);
#pragma unroll
        for (int q = 0; q < 4; q++) {
            float2 f = h2f((&v.x)[q]);
            acc[q * 2 + 0] += f.x; acc[q * 2 + 1] += f.y;
        }
    }

    float rd = g_rdeg[node];
    float4 o0, o1;
    o0.x = acc[0] * rd; o0.y = acc[1] * rd; o0.z = acc[2] * rd; o0.w = acc[3] * rd;
    o1.x = acc[4] * rd; o1.y = acc[5] * rd; o1.z = acc[6] * rd; o1.w = acc[7] * rd;
    float* dst = g_agg + (size_t)node * HID + c;
    *(float4*)dst       = o0;
    *(float4*)(dst + 4) = o1;
}

// -------- fused GEMM with packed f32x2 FMAs; weights pre-duplicated in smem --------
// out[n,o] = act( sum_k rowcat[n,k]*Wcat[o,k] + bias[o] (+bias2[o]) )
// rowcat = [agg_row | x_row] (bSel>=0) or plain 128-wide A row (bSel<0).
// shadowSel: 0 -> also write g_h0, 1 -> g_h1, -1 -> none.
__global__ void __launch_bounds__(128) gemm_kernel(
        const float* __restrict__ Aext, int aSel, int lda, int bSel,
        const float* __restrict__ W0, const float* __restrict__ W1,
        const float* __restrict__ bias, const float* __restrict__ bias2,
        float* __restrict__ outExt, int outSel, int outRowOff, int relu,
        int shadowSel) {
    extern __shared__ ull smp[];
    ull*   Wd   = smp;                         // [64][WD_LD] dup'd weights
    float* rows = (float*)(smp + 64 * WD_LD);  // [128][ROWS_LD]

    const float* __restrict__ A = (aSel == 2) ? g_agg : Aext;
    const float* __restrict__ B = (bSel == 0) ? g_x : (bSel == 1 ? g_y : nullptr);
    float* __restrict__ O = (outSel == 0) ? g_x : (outSel == 1 ? g_y : outExt);
    __half* __restrict__ S = (shadowSel == 0) ? g_h0 : (shadowSel == 1 ? g_h1 : nullptr);

    const int tid = threadIdx.x;
    const int tx  = tid & 15;
    const int ty  = tid >> 4;
    const int nodeBase = blockIdx.x * 32;

    for (int it = 0; it < 32; it++) {
        int node = nodeBase + it;
        int k = tid;
        float v;
        if (B) v = (k < HID) ? A[(size_t)node * lda + k]
                             : B[(size_t)node * HID + (k - HID)];
        else   v = A[(size_t)node * lda + k];
        rows[k * ROWS_LD + it] = v;
    }

    ull a01[4], a23[4];
#pragma unroll
    for (int i = 0; i < 4; i++) { a01[i] = 0ull; a23[i] = 0ull; }

    for (int h = 0; h < 2; h++) {
        __syncthreads();
        const float* Wsrc; int wstride, koff;
        if (W1) { Wsrc = h ? W1 : W0; wstride = 64;  koff = 0; }
        else    { Wsrc = W0;          wstride = 128; koff = h * 64; }
        for (int idx = tid; idx < 64 * 64; idx += 128) {
            int o = idx >> 6, k = idx & 63;
            Wd[k * WD_LD + o] = dup_f32(Wsrc[(size_t)o * wstride + koff + k]);
        }
        __syncthreads();
#pragma unroll 8
        for (int k = 0; k < 64; k++) {
            ulonglong2 rp = *(const ulonglong2*)&rows[((h << 6) + k) * ROWS_LD + ty * 4];
            const ull* wr = Wd + k * WD_LD + tx * 4;
            ulonglong2 wA = *(const ulonglong2*)wr;
            ulonglong2 wB = *(const ulonglong2*)(wr + 2);
            ffma2(a01[0], rp.x, wA.x); ffma2(a23[0], rp.y, wA.x);
            ffma2(a01[1], rp.x, wA.y); ffma2(a23[1], rp.y, wA.y);
            ffma2(a01[2], rp.x, wB.x); ffma2(a23[2], rp.y, wB.x);
            ffma2(a01[3], rp.x, wB.y); ffma2(a23[3], rp.y, wB.y);
        }
    }

    const int o = tx * 4;
    float b0 = bias[o], b1 = bias[o + 1], b2 = bias[o + 2], b3 = bias[o + 3];
    if (bias2) { b0 += bias2[o]; b1 += bias2[o + 1]; b2 += bias2[o + 2]; b3 += bias2[o + 3]; }

    float res[4][4];
#pragma unroll
    for (int i = 0; i < 4; i++) {
        float2 p = unpack2(a01[i]);
        float2 q = unpack2(a23[i]);
        res[0][i] = p.x; res[1][i] = p.y; res[2][i] = q.x; res[3][i] = q.y;
    }
#pragma unroll
    for (int j = 0; j < 4; j++) {
        size_t row = (size_t)(nodeBase + ty * 4 + j + outRowOff) * HID;
        float4 r;
        r.x = res[j][0] + b0; r.y = res[j][1] + b1;
        r.z = res[j][2] + b2; r.w = res[j][3] + b3;
        if (relu) {
            r.x = fmaxf(r.x, 0.f); r.y = fmaxf(r.y, 0.f);
            r.z = fmaxf(r.z, 0.f); r.w = fmaxf(r.w, 0.f);
        }
        *(float4*)(O + row + o) = r;
        if (S) {
            uint2 hh; hh.x = f2h2(r.x, r.y); hh.y = f2h2(r.z, r.w);
            *(uint2*)(S + row + o) = hh;
        }
    }
}

extern "C" void kernel_launch(void* const* d_in, const int* in_sizes, int n_in,
                              void* d_out, int out_size) {
    const float* track_x   = (const float*)d_in[0];
    const int*   pl_tr_src = (const int*)d_in[1];
    const int*   pl_tr_dst = (const int*)d_in[2];
    const int*   tr_ar_src = (const int*)d_in[3];
    const int*   tr_ar_dst = (const int*)d_in[4];
    const float* pl_emb    = (const float*)d_in[5];
    const float* ar_emb    = (const float*)d_in[6];
    const float* track_W   = (const float*)d_in[7];
    const float* track_b   = (const float*)d_in[8];
    const float* type_emb  = (const float*)d_in[9];
    const float* conv_Wl   = (const float*)d_in[10];
    const float* conv_bl   = (const float*)d_in[11];
    const float* conv_Wr   = (const float*)d_in[12];
    float* out = (float*)d_out;

    const int E1 = in_sizes[1];
    const int E2 = in_sizes[3];
    const int ET = E1 + E2;

    cudaFuncSetAttribute(gemm_kernel,
                         cudaFuncAttributeMaxDynamicSharedMemorySize, GEMM_SMEM);

    // lazily created side stream + events for capture-fork overlap
    static cudaStream_t s2 = nullptr;
    static cudaEvent_t evFork = nullptr, evJoin = nullptr;
    if (s2 == nullptr) {
        cudaStreamCreateWithFlags(&s2, cudaStreamNonBlocking);
        cudaEventCreateWithFlags(&evFork, cudaEventDisableTiming);
        cudaEventCreateWithFlags(&evJoin, cudaEventDisableTiming);
    }

    bool fork = (s2 != nullptr && evFork != nullptr && evJoin != nullptr);
    cudaStream_t sCsr = fork ? s2 : (cudaStream_t)0;
    if (fork) {
        cudaEventRecord(evFork, 0);
        cudaStreamWaitEvent(s2, evFork, 0);
    }

    // ---- branch A (default stream): node features (fp32 + fp16 shadow) ----
    {
        int total = (NUM_PL + NUM_AR) * (HID / 4);
        init_emb_kernel<<<(total + 255) / 256, 256>>>(pl_emb, ar_emb, type_emb);
    }
    gemm_kernel<<<NUM_TR / 32, 128, GEMM_SMEM>>>(track_x, -1, 128, /*bSel*/-1,
                                                 track_W, nullptr,
                                                 track_b, type_emb + HID,
                                                 nullptr, /*outSel*/0, OFF_TR,
                                                 /*relu*/0, /*shadowSel*/0);

    // ---- branch B (side stream): degrees + CSR ----
    zero_deg_kernel<<<(NTOT + 255) / 256, 256, 0, sCsr>>>();
    deg_kernel<<<(ET + 255) / 256, 256, 0, sCsr>>>(pl_tr_src, pl_tr_dst, E1,
                                                   tr_ar_src, tr_ar_dst, E2);
    scan_pass1<<<NB, SCAN_B, 0, sCsr>>>();
    scan_pass2<<<1, 256, 0, sCsr>>>();
    scan_pass3<<<NB, SCAN_B, 0, sCsr>>>();
    fill_kernel<<<(ET + 255) / 256, 256, 0, sCsr>>>(pl_tr_src, pl_tr_dst, E1,
                                                    tr_ar_src, tr_ar_dst, E2);
    if (fork) {
        cudaEventRecord(evJoin, s2);
        cudaStreamWaitEvent((cudaStream_t)0, evJoin, 0);
    }

    // ---- layer 0: g_h0/g_x -> g_y (+g_h1) ----
    gather_kernel<<<(NTOT * 8 + 255) / 256, 256>>>(0);
    gemm_kernel<<<NTOT / 32, 128, GEMM_SMEM>>>(nullptr, 2, HID, /*bSel*/0,
                                               conv_Wl, conv_Wr, conv_bl, nullptr,
                                               nullptr, /*outSel*/1, 0, /*relu*/1,
                                               /*shadowSel*/1);

    // ---- layer 1: g_h1/g_y -> d_out ----
    gather_kernel<<<(NTOT * 8 + 255) / 256, 256>>>(1);
    gemm_kernel<<<NTOT / 32, 128, GEMM_SMEM>>>(nullptr, 2, HID, /*bSel*/1,
                                               conv_Wl + 64 * 64, conv_Wr + 64 * 64,
                                               conv_bl + 64, nullptr,
                                               out, /*outSel*/-1, 0, /*relu*/1,
                                               /*shadowSel*/-1);
}

// round 8
// speedup vs baseline: 1.7628x; 1.7628x over previous
#include <cuda_runtime.h>
#include <cuda_fp16.h>

#define NUM_PL 50000
#define NUM_TR 100000
#define NUM_AR 10000
#define OFF_TR NUM_PL
#define OFF_AR (NUM_PL + NUM_TR)
#define NTOT   (NUM_PL + NUM_TR + NUM_AR)
#define HID    64
#define NADJ   4200000
#define SCAN_B 1024
#define NB     ((NTOT + SCAN_B - 1) / SCAN_B)   // 157

typedef unsigned long long ull;

// -------- scratch (device globals; no runtime allocation) --------
__device__ __align__(16) float  g_x  [(size_t)NTOT * HID];
__device__ __align__(16) float  g_y  [(size_t)NTOT * HID];
__device__ __align__(16) float  g_agg[(size_t)NTOT * HID];
__device__ __align__(16) __half g_h0 [(size_t)NTOT * HID];
__device__ __align__(16) __half g_h1 [(size_t)NTOT * HID];
__device__ int   g_deg [NTOT];
__device__ float g_rdeg[NTOT];
__device__ int   g_ptr [NTOT];
__device__ int   g_cur [NTOT];
__device__ __align__(16) int g_adj [NADJ];
__device__ int   g_bsum[NB];

// -------- helpers --------
__device__ __forceinline__ ull dup_f32(float x) {
    ull r; asm("mov.b64 %0, {%1,%1};" : "=l"(r) : "f"(x)); return r;
}
__device__ __forceinline__ void ffma2(ull& d, ull a, ull b) {
    asm("fma.rn.f32x2 %0, %1, %2, %3;" : "=l"(d) : "l"(a), "l"(b), "l"(d));
}
__device__ __forceinline__ float2 unpack2(ull v) {
    float2 f; asm("mov.b64 {%0,%1}, %2;" : "=f"(f.x), "=f"(f.y) : "l"(v)); return f;
}
__device__ __forceinline__ float2 h2f(unsigned u) {
    return __half22float2(*(const __half2*)&u);
}
__device__ __forceinline__ __half2 u2h(unsigned u) {
    return *(const __half2*)&u;
}
__device__ __forceinline__ unsigned f2h2(float a, float b) {
    __half2 h = __floats2half2_rn(a, b);
    return *(const unsigned*)&h;
}

// -------- init playlist & artist rows --------
__global__ void init_emb_kernel(const float* __restrict__ pl_emb,
                                const float* __restrict__ ar_emb,
                                const float* __restrict__ type_emb) {
    int t = blockIdx.x * blockDim.x + threadIdx.x;
    int total = (NUM_PL + NUM_AR) * (HID / 4);
    if (t >= total) return;
    int node = t >> 4;
    int c    = (t & 15) * 4;
    const float* src; const float* ty; size_t row;
    if (node < NUM_PL) {
        src = pl_emb + (size_t)node * HID;
        row = (size_t)node * HID;
        ty  = type_emb;
    } else {
        int a = node - NUM_PL;
        src = ar_emb + (size_t)a * HID;
        row = (size_t)(OFF_AR + a) * HID;
        ty  = type_emb + 2 * HID;
    }
    float4 v  = *(const float4*)(src + c);
    float4 tv = *(const float4*)(ty  + c);
    v.x += tv.x; v.y += tv.y; v.z += tv.z; v.w += tv.w;
    *(float4*)(g_x + row + c) = v;
    uint2 h; h.x = f2h2(v.x, v.y); h.y = f2h2(v.z, v.w);
    *(uint2*)(g_h0 + row + c) = h;
}

__global__ void zero_deg_kernel() {
    int i = blockIdx.x * blockDim.x + threadIdx.x;
    if (i < NTOT) g_deg[i] = 0;
}

__global__ void deg_kernel(const int* __restrict__ s1, const int* __restrict__ d1, int n1,
                           const int* __restrict__ s2, const int* __restrict__ d2, int n2) {
    int e = blockIdx.x * blockDim.x + threadIdx.x;
    int a, b;
    if (e < n1)           { a = __ldg(s1 + e);               b = __ldg(d1 + e) + OFF_TR; }
    else if (e < n1 + n2) { a = __ldg(s2 + e - n1) + OFF_TR; b = __ldg(d2 + e - n1) + OFF_AR; }
    else return;
    atomicAdd(&g_deg[a], 1);
    atomicAdd(&g_deg[b], 1);
}

// -------- 2-pass scan (pass2 folded into pass3) --------
__device__ __forceinline__ int block_incl_scan(int v, int* warpsums) {
    int lane = threadIdx.x & 31, wid = threadIdx.x >> 5;
    int x = v;
#pragma unroll
    for (int o = 1; o < 32; o <<= 1) {
        int y = __shfl_up_sync(0xffffffffu, x, o);
        if (lane >= o) x += y;
    }
    if (lane == 31) warpsums[wid] = x;
    __syncthreads();
    if (threadIdx.x < 32) {
        int w = warpsums[threadIdx.x];
#pragma unroll
        for (int o = 1; o < 32; o <<= 1) {
            int y = __shfl_up_sync(0xffffffffu, w, o);
            if (threadIdx.x >= o) w += y;
        }
        warpsums[threadIdx.x] = w;
    }
    __syncthreads();
    if (wid > 0) x += warpsums[wid - 1];
    return x;
}

__global__ void scan_pass1() {
    __shared__ int warpsums[32];
    int i = blockIdx.x * SCAN_B + threadIdx.x;
    int v = (i < NTOT) ? g_deg[i] : 0;
    int x = block_incl_scan(v, warpsums);
    if (threadIdx.x == SCAN_B - 1) g_bsum[blockIdx.x] = x;
}

__global__ void scan_pass3() {
    __shared__ int warpsums[32];
    __shared__ int boff_s;
    // fold of old scan_pass2: every block scans the NB block sums and keeps
    // the exclusive prefix at its own block index.
    {
        int bv = (threadIdx.x < NB) ? g_bsum[threadIdx.x] : 0;
        int bx = block_incl_scan(bv, warpsums);
        if (threadIdx.x == blockIdx.x) boff_s = bx - bv;
    }
    __syncthreads();
    int i = blockIdx.x * SCAN_B + threadIdx.x;
    int v = (i < NTOT) ? g_deg[i] : 0;
    int x = block_incl_scan(v, warpsums);
    if (i < NTOT) {
        int excl = x - v + boff_s;
        g_ptr[i] = excl;
        g_cur[i] = excl;
        g_rdeg[i] = 1.0f / (float)(v > 0 ? v : 1);
    }
}

__global__ void fill_kernel(const int* __restrict__ s1, const int* __restrict__ d1, int n1,
                            const int* __restrict__ s2, const int* __restrict__ d2, int n2) {
    int e = blockIdx.x * blockDim.x + threadIdx.x;
    int a, b;
    if (e < n1)           { a = __ldg(s1 + e);               b = __ldg(d1 + e) + OFF_TR; }
    else if (e < n1 + n2) { a = __ldg(s2 + e - n1) + OFF_TR; b = __ldg(d2 + e - n1) + OFF_AR; }
    else return;
    int pa = atomicAdd(&g_cur[a], 1);
    g_adj[pa] = b;
    int pb = atomicAdd(&g_cur[b], 1);
    g_adj[pb] = a;
}

// -------- gather aggregation: 8 lanes/node, HADD2 tree per 4 neighbors --------
__global__ void gather_kernel(int layer) {
    const __half* __restrict__ H = layer ? g_h1 : g_h0;
    int t = blockIdx.x * blockDim.x + threadIdx.x;
    int node = t >> 3;
    if (node >= NTOT) return;
    int c = (t & 7) * 8;             // half-column offset (each lane owns 8 halves = 16B)
    int beg = g_ptr[node];
    int d   = g_deg[node];
    float acc[8];
#pragma unroll
    for (int j = 0; j < 8; j++) acc[j] = 0.f;

    int i = 0;
    int mis = beg & 3;
    int peel = mis ? (4 - mis) : 0;
    if (peel > d) peel = d;
    for (; i < peel; i++) {
        int s = __ldg(g_adj + beg + i);
        uint4 v = *(const uint4*)(H + (size_t)s * HID + c);
#pragma unroll
        for (int q = 0; q < 4; q++) {
            float2 f = h2f((&v.x)[q]);
            acc[q * 2 + 0] += f.x; acc[q * 2 + 1] += f.y;
        }
    }
    for (; i + 4 <= d; i += 4) {
        int4 s = *(const int4*)(g_adj + beg + i);
        uint4 v0 = *(const uint4*)(H + (size_t)s.x * HID + c);
        uint4 v1 = *(const uint4*)(H + (size_t)s.y * HID + c);
        uint4 v2 = *(const uint4*)(H + (size_t)s.z * HID + c);
        uint4 v3 = *(const uint4*)(H + (size_t)s.w * HID + c);
#pragma unroll
        for (int q = 0; q < 4; q++) {
            __half2 sh = __hadd2(__hadd2(u2h((&v0.x)[q]), u2h((&v1.x)[q])),
                                 __hadd2(u2h((&v2.x)[q]), u2h((&v3.x)[q])));
            float2 f = __half22float2(sh);
            acc[q * 2 + 0] += f.x; acc[q * 2 + 1] += f.y;
        }
    }
    for (; i < d; i++) {
        int s = __ldg(g_adj + beg + i);
        uint4 v = *(const uint4*)(H + (size_t)s * HID + c);
#pragma unroll
        for (int q = 0; q < 4; q++) {
            float2 f = h2f((&v.x)[q]);
            acc[q * 2 + 0] += f.x; acc[q * 2 + 1] += f.y;
        }
    }

    float rd = g_rdeg[node];
    float4 o0, o1;
    o0.x = acc[0] * rd; o0.y = acc[1] * rd; o0.z = acc[2] * rd; o0.w = acc[3] * rd;
    o1.x = acc[4] * rd; o1.y = acc[5] * rd; o1.z = acc[6] * rd; o1.w = acc[7] * rd;
    float* dst = g_agg + (size_t)node * HID + c;
    *(float4*)dst       = o0;
    *(float4*)(dst + 4) = o1;
}

// -------- fused GEMM with packed f32x2 FMAs (static smem, r5 layout) --------
// out[n,o] = act( sum_k rowcat[n,k]*Wcat[o,k] + bias[o] (+bias2[o]) )
// rowcat = [agg_row | x_row] (bSel>=0) or plain 128-wide A row (bSel<0).
// shadowSel: 0 -> also write g_h0, 1 -> g_h1, -1 -> none.
__global__ void __launch_bounds__(128) gemm_kernel(
        const float* __restrict__ Aext, int aSel, int lda, int bSel,
        const float* __restrict__ W0, const float* __restrict__ W1,
        const float* __restrict__ bias, const float* __restrict__ bias2,
        float* __restrict__ outExt, int outSel, int outRowOff, int relu,
        int shadowSel) {
    __shared__ float Ws[64][68];
    __shared__ float rows[128][36];

    const float* __restrict__ A = (aSel == 2) ? g_agg : Aext;
    const float* __restrict__ B = (bSel == 0) ? g_x : (bSel == 1 ? g_y : nullptr);
    float* __restrict__ O = (outSel == 0) ? g_x : (outSel == 1 ? g_y : outExt);
    __half* __restrict__ S = (shadowSel == 0) ? g_h0 : (shadowSel == 1 ? g_h1 : nullptr);

    const int tid = threadIdx.x;
    const int tx  = tid & 15;
    const int ty  = tid >> 4;
    const int nodeBase = blockIdx.x * 32;

    for (int it = 0; it < 32; it++) {
        int node = nodeBase + it;
        int k = tid;
        float v;
        if (B) v = (k < HID) ? A[(size_t)node * lda + k]
                             : B[(size_t)node * HID + (k - HID)];
        else   v = A[(size_t)node * lda + k];
        rows[k][it] = v;
    }

    ull a01[4], a23[4];
#pragma unroll
    for (int i = 0; i < 4; i++) { a01[i] = 0ull; a23[i] = 0ull; }

    for (int h = 0; h < 2; h++) {
        __syncthreads();
        const float* Wsrc; int wstride, koff;
        if (W1) { Wsrc = h ? W1 : W0; wstride = 64;  koff = 0; }
        else    { Wsrc = W0;          wstride = 128; koff = h * 64; }
        for (int idx = tid; idx < 64 * 64; idx += 128) {
            int o = idx >> 6, k = idx & 63;
            Ws[k][o] = Wsrc[(size_t)o * wstride + koff + k];
        }
        __syncthreads();
#pragma unroll 8
        for (int k = 0; k < 64; k++) {
            ulonglong2 rp = *(const ulonglong2*)&rows[(h << 6) + k][ty * 4];
            float4 w = *(const float4*)&Ws[k][tx * 4];
            ull w0 = dup_f32(w.x), w1 = dup_f32(w.y);
            ull w2 = dup_f32(w.z), w3 = dup_f32(w.w);
            ffma2(a01[0], rp.x, w0); ffma2(a23[0], rp.y, w0);
            ffma2(a01[1], rp.x, w1); ffma2(a23[1], rp.y, w1);
            ffma2(a01[2], rp.x, w2); ffma2(a23[2], rp.y, w2);
            ffma2(a01[3], rp.x, w3); ffma2(a23[3], rp.y, w3);
        }
    }

    const int o = tx * 4;
    float b0 = bias[o], b1 = bias[o + 1], b2 = bias[o + 2], b3 = bias[o + 3];
    if (bias2) { b0 += bias2[o]; b1 += bias2[o + 1]; b2 += bias2[o + 2]; b3 += bias2[o + 3]; }

    float res[4][4];
#pragma unroll
    for (int i = 0; i < 4; i++) {
        float2 p = unpack2(a01[i]);
        float2 q = unpack2(a23[i]);
        res[0][i] = p.x; res[1][i] = p.y; res[2][i] = q.x; res[3][i] = q.y;
    }
#pragma unroll
    for (int j = 0; j < 4; j++) {
        size_t row = (size_t)(nodeBase + ty * 4 + j + outRowOff) * HID;
        float4 r;
        r.x = res[j][0] + b0; r.y = res[j][1] + b1;
        r.z = res[j][2] + b2; r.w = res[j][3] + b3;
        if (relu) {
            r.x = fmaxf(r.x, 0.f); r.y = fmaxf(r.y, 0.f);
            r.z = fmaxf(r.z, 0.f); r.w = fmaxf(r.w, 0.f);
        }
        *(float4*)(O + row + o) = r;
        if (S) {
            uint2 hh; hh.x = f2h2(r.x, r.y); hh.y = f2h2(r.z, r.w);
            *(uint2*)(S + row + o) = hh;
        }
    }
}

extern "C" void kernel_launch(void* const* d_in, const int* in_sizes, int n_in,
                              void* d_out, int out_size) {
    const float* track_x   = (const float*)d_in[0];
    const int*   pl_tr_src = (const int*)d_in[1];
    const int*   pl_tr_dst = (const int*)d_in[2];
    const int*   tr_ar_src = (const int*)d_in[3];
    const int*   tr_ar_dst = (const int*)d_in[4];
    const float* pl_emb    = (const float*)d_in[5];
    const float* ar_emb    = (const float*)d_in[6];
    const float* track_W   = (const float*)d_in[7];
    const float* track_b   = (const float*)d_in[8];
    const float* type_emb  = (const float*)d_in[9];
    const float* conv_Wl   = (const float*)d_in[10];
    const float* conv_bl   = (const float*)d_in[11];
    const float* conv_Wr   = (const float*)d_in[12];
    float* out = (float*)d_out;

    const int E1 = in_sizes[1];
    const int E2 = in_sizes[3];
    const int ET = E1 + E2;

    // lazily created side stream + events for capture-fork overlap
    static cudaStream_t s2 = nullptr;
    static cudaEvent_t evFork = nullptr, evJoin = nullptr;
    if (s2 == nullptr) {
        cudaStreamCreateWithFlags(&s2, cudaStreamNonBlocking);
        cudaEventCreateWithFlags(&evFork, cudaEventDisableTiming);
        cudaEventCreateWithFlags(&evJoin, cudaEventDisableTiming);
    }

    bool fork = (s2 != nullptr && evFork != nullptr && evJoin != nullptr);
    cudaStream_t sCsr = fork ? s2 : (cudaStream_t)0;
    if (fork) {
        cudaEventRecord(evFork, 0);
        cudaStreamWaitEvent(s2, evFork, 0);
    }

    // ---- branch A (default stream): node features (fp32 + fp16 shadow) ----
    {
        int total = (NUM_PL + NUM_AR) * (HID / 4);
        init_emb_kernel<<<(total + 255) / 256, 256>>>(pl_emb, ar_emb, type_emb);
    }
    gemm_kernel<<<NUM_TR / 32, 128>>>(track_x, -1, 128, /*bSel*/-1,
                                      track_W, nullptr,
                                      track_b, type_emb + HID,
                                      nullptr, /*outSel*/0, OFF_TR, /*relu*/0,
                                      /*shadowSel*/0);

    // ---- branch B (side stream): degrees + CSR ----
    zero_deg_kernel<<<(NTOT + 255) / 256, 256, 0, sCsr>>>();
    deg_kernel<<<(ET + 255) / 256, 256, 0, sCsr>>>(pl_tr_src, pl_tr_dst, E1,
                                                   tr_ar_src, tr_ar_dst, E2);
    scan_pass1<<<NB, SCAN_B, 0, sCsr>>>();
    scan_pass3<<<NB, SCAN_B, 0, sCsr>>>();
    fill_kernel<<<(ET + 255) / 256, 256, 0, sCsr>>>(pl_tr_src, pl_tr_dst, E1,
                                                    tr_ar_src, tr_ar_dst, E2);
    if (fork) {
        cudaEventRecord(evJoin, s2);
        cudaStreamWaitEvent((cudaStream_t)0, evJoin, 0);
    }

    // ---- layer 0: g_h0/g_x -> g_y (+g_h1) ----
    gather_kernel<<<(NTOT * 8 + 255) / 256, 256>>>(0);
    gemm_kernel<<<NTOT / 32, 128>>>(nullptr, 2, HID, /*bSel*/0,
                                    conv_Wl, conv_Wr, conv_bl, nullptr,
                                    nullptr, /*outSel*/1, 0, /*relu*/1,
                                    /*shadowSel*/1);

    // ---- layer 1: g_h1/g_y -> d_out ----
    gather_kernel<<<(NTOT * 8 + 255) / 256, 256>>>(1);
    gemm_kernel<<<NTOT / 32, 128>>>(nullptr, 2, HID, /*bSel*/1,
                                    conv_Wl + 64 * 64, conv_Wr + 64 * 64,
                                    conv_bl + 64, nullptr,
                                    out, /*outSel*/-1, 0, /*relu*/1,
                                    /*shadowSel*/-1);
}